// round 10
// baseline (speedup 1.0000x reference)
#include <cuda_runtime.h>
#include <cuda_fp16.h>
#include <cstdint>

// Problem constants (shapes are fixed by the dataset).
#define NN 100000
#define EE 1600000
#define HD 64
#define SCAN_CHUNK 1024
#define MAX_SCAN_BLOCKS 128
#define GROWS 64    // GEMM rows per block (64*68*4 + 64*68*4 = 34816B smem < 48KB)

// ---------------- scratch (device globals: allocation-free) ----------------
__device__ int    g_is64;
__device__ int    g_src32[EE];
__device__ int    g_dst32[EE];
__device__ int    g_cnt[NN];
__device__ int    g_rowstart[NN + 1];
__device__ int    g_cursor[NN];
__device__ float  g_dis[NN];
__device__ int    g_blocksum[MAX_SCAN_BLOCKS];
__device__ int    g_blockoff[MAX_SCAN_BLOCKS];
__device__ int2   g_epack[EE];                 // packed (src, weight-bits) per edge
__device__ __half g_bufAh[(size_t)NN * HD];    // fp16 GEMM output (gather input)
__device__ float  g_bufB[(size_t)NN * HD];     // fp32 gather output (GEMM input)

// ---------------- dtype sniff: int64 edge_index has zero high words ----------------
__global__ void k_detect(const void* ei) {
    __shared__ int nz;
    if (threadIdx.x == 0) nz = 0;
    __syncthreads();
    unsigned v = ((const unsigned*)ei)[2 * threadIdx.x + 1];
    if (v != 0) atomicOr(&nz, 1);
    __syncthreads();
    if (threadIdx.x == 0) g_is64 = (nz == 0) ? 1 : 0;
}

__global__ void k_zero_int(int* p, int n) {
    int i = blockIdx.x * blockDim.x + threadIdx.x;
    if (i < n) p[i] = 0;
}

// ---------------- convert edge_index to int32 src/dst AND histogram dst ----------------
__global__ void k_convhist(const void* ei, int e, int n, int* __restrict__ cnt) {
    int i = blockIdx.x * blockDim.x + threadIdx.x;
    if (i >= e) return;
    int s, d;
    if (g_is64) {
        const long long* p = (const long long*)ei;
        s = (int)p[i];
        d = (int)p[(size_t)e + i];
    } else {
        const int* p = (const int*)ei;
        s = p[i];
        d = p[e + i];
    }
    g_src32[i] = s;
    g_dst32[i] = d;
    if ((unsigned)d < (unsigned)n) atomicAdd(&cnt[d], 1);
}

// ---------------- 3-phase parallel scan over cnt ----------------
__global__ void __launch_bounds__(SCAN_CHUNK) k_scan1(const int* __restrict__ cnt,
                                                      int* __restrict__ rowstart,
                                                      int* __restrict__ blocksum,
                                                      float* __restrict__ dis, int n) {
    __shared__ int sh[SCAN_CHUNK];
    int t = threadIdx.x;
    int i = blockIdx.x * SCAN_CHUNK + t;
    int v = (i < n) ? cnt[i] : 0;
    if (i < n) dis[i] = rsqrtf((float)v + 1.0f);
    sh[t] = v;
    __syncthreads();
    #pragma unroll
    for (int off = 1; off < SCAN_CHUNK; off <<= 1) {
        int add = (t >= off) ? sh[t - off] : 0;
        __syncthreads();
        sh[t] += add;
        __syncthreads();
    }
    if (i < n) rowstart[i] = sh[t] - v;
    if (t == SCAN_CHUNK - 1) blocksum[blockIdx.x] = sh[SCAN_CHUNK - 1];
}

__global__ void k_scan2(const int* __restrict__ blocksum, int* __restrict__ blockoff,
                        int nb, int* __restrict__ rowstart, int n) {
    __shared__ int sh[MAX_SCAN_BLOCKS];
    int t = threadIdx.x;
    int v = (t < nb) ? blocksum[t] : 0;
    sh[t] = v;
    __syncthreads();
    #pragma unroll
    for (int off = 1; off < MAX_SCAN_BLOCKS; off <<= 1) {
        int add = (t >= off) ? sh[t - off] : 0;
        __syncthreads();
        sh[t] += add;
        __syncthreads();
    }
    if (t < nb) blockoff[t] = sh[t] - v;
    if (t == MAX_SCAN_BLOCKS - 1) rowstart[n] = sh[MAX_SCAN_BLOCKS - 1];
}

__global__ void __launch_bounds__(SCAN_CHUNK) k_scan3(int* __restrict__ rowstart,
                                                      int* __restrict__ cursor,
                                                      const int* __restrict__ blockoff, int n) {
    int i = blockIdx.x * SCAN_CHUNK + threadIdx.x;
    if (i < n) {
        int r = rowstart[i] + blockoff[blockIdx.x];
        rowstart[i] = r;
        cursor[i]   = r;
    }
}

// ---------------- CSR fill: one packed STG.64 per edge ----------------
__global__ void k_fill(const int* __restrict__ src, const int* __restrict__ dst,
                       int e, int n, const float* __restrict__ dis,
                       int* __restrict__ cursor, int2* __restrict__ epack) {
    int i = blockIdx.x * blockDim.x + threadIdx.x;
    if (i < e) {
        int s = src[i];
        int d = dst[i];
        if ((unsigned)s >= (unsigned)n || (unsigned)d >= (unsigned)n) return;
        float w = dis[s] * dis[d];
        int p = atomicAdd(&cursor[d], 1);
        epack[p] = make_int2(s, __float_as_int(w));
    }
}

// ---------------- tf32 helpers ----------------
__device__ __forceinline__ float to_tf32(float x) {
    unsigned r;
    asm("cvt.rna.tf32.f32 %0, %1;" : "=r"(r) : "f"(x));
    return __uint_as_float(r);
}

__device__ __forceinline__ void mma_tf32(float* c, unsigned a0, unsigned a1,
                                         unsigned a2, unsigned a3,
                                         unsigned b0, unsigned b1) {
    asm volatile(
        "mma.sync.aligned.m16n8k8.row.col.f32.tf32.tf32.f32 "
        "{%0,%1,%2,%3}, {%4,%5,%6,%7}, {%8,%9}, {%0,%1,%2,%3};"
        : "+f"(c[0]), "+f"(c[1]), "+f"(c[2]), "+f"(c[3])
        : "r"(a0), "r"(a1), "r"(a2), "r"(a3), "r"(b0), "r"(b1));
}

// ---------------- GEMM (tf32 tensor core): Yh[n,64] = act(X)[n,64] @ W[64,64] ----------------
__global__ void __launch_bounds__(128) k_gemm_tc(const float* __restrict__ X,
                                                 const float* __restrict__ W,
                                                 __half* __restrict__ Y, int n, int relu_in) {
    __shared__ float sA[GROWS * 68];
    __shared__ float sB[64 * 68];

    int t    = threadIdx.x;
    int row0 = blockIdx.x * GROWS;

    #pragma unroll
    for (int i = 0; i < 8; i++) {
        int idx = i * 512 + t * 4;
        float4 v = *(const float4*)&W[idx];
        int k  = idx >> 6;
        int nn = idx & 63;
        sB[k * 68 + nn + 0] = to_tf32(v.x);
        sB[k * 68 + nn + 1] = to_tf32(v.y);
        sB[k * 68 + nn + 2] = to_tf32(v.z);
        sB[k * 68 + nn + 3] = to_tf32(v.w);
    }
    {
        int kc = (t & 15) * 4;
        int rl = t >> 4;
        #pragma unroll
        for (int i = 0; i < 8; i++) {
            int r  = rl + i * 8;
            int gr = row0 + r;
            float4 v = make_float4(0.f, 0.f, 0.f, 0.f);
            if (gr < n) v = *(const float4*)&X[(size_t)gr * HD + kc];
            if (relu_in) {
                v.x = fmaxf(v.x, 0.f); v.y = fmaxf(v.y, 0.f);
                v.z = fmaxf(v.z, 0.f); v.w = fmaxf(v.w, 0.f);
            }
            sA[r * 68 + kc + 0] = to_tf32(v.x);
            sA[r * 68 + kc + 1] = to_tf32(v.y);
            sA[r * 68 + kc + 2] = to_tf32(v.z);
            sA[r * 68 + kc + 3] = to_tf32(v.w);
        }
    }
    __syncthreads();

    int warp = t >> 5, lane = t & 31;
    int g  = lane >> 2;
    int tq = lane & 3;
    int mrow = warp * 16;

    float c[8][4];
    #pragma unroll
    for (int nf = 0; nf < 8; nf++)
        #pragma unroll
        for (int j = 0; j < 4; j++) c[nf][j] = 0.f;

    #pragma unroll
    for (int kk = 0; kk < 8; kk++) {
        int k0 = kk * 8;
        unsigned a0 = __float_as_uint(sA[(mrow + g)     * 68 + k0 + tq]);
        unsigned a1 = __float_as_uint(sA[(mrow + g + 8) * 68 + k0 + tq]);
        unsigned a2 = __float_as_uint(sA[(mrow + g)     * 68 + k0 + tq + 4]);
        unsigned a3 = __float_as_uint(sA[(mrow + g + 8) * 68 + k0 + tq + 4]);
        #pragma unroll
        for (int nf = 0; nf < 8; nf++) {
            unsigned b0 = __float_as_uint(sB[(k0 + tq)     * 68 + nf * 8 + g]);
            unsigned b1 = __float_as_uint(sB[(k0 + tq + 4) * 68 + nf * 8 + g]);
            mma_tf32(c[nf], a0, a1, a2, a3, b0, b1);
        }
    }

    int gr0 = row0 + mrow + g;
    int gr1 = gr0 + 8;
    #pragma unroll
    for (int nf = 0; nf < 8; nf++) {
        int colb = nf * 8 + 2 * tq;
        if (gr0 < n) {
            __half2 h = __floats2half2_rn(c[nf][0], c[nf][1]);
            *(__half2*)&Y[(size_t)gr0 * HD + colb] = h;
        }
        if (gr1 < n) {
            __half2 h = __floats2half2_rn(c[nf][2], c[nf][3]);
            *(__half2*)&Y[(size_t)gr1 * HD + colb] = h;
        }
    }
}

// ---------------- Gather: one warp per node, QUARTER-WARP per edge (fp16 rows) ----------------
// 4 independent edge chains per warp + software-pipelined index prefetch.
// Y[i] = sum_{e in CSR(i)} A[src_e]*w_e  +  A[i]*dis[i]^2  +  b   (fp32 accumulate)
__global__ void __launch_bounds__(256) k_gather(const __half* __restrict__ A,
                                                const int* __restrict__ rowstart,
                                                const int2* __restrict__ epack,
                                                const float* __restrict__ dis,
                                                const float* __restrict__ bias,
                                                float* __restrict__ Y, int n) {
    int wid  = (blockIdx.x * blockDim.x + threadIdx.x) >> 5;
    int lane = threadIdx.x & 31;
    if (wid >= n) return;

    int q   = lane >> 3;        // quarter id 0..3 (edge slot)
    int ql  = lane & 7;         // lane within quarter
    int col = ql * 8;           // 8 fp16 channels per lane (16 bytes)

    float acc[8];
    #pragma unroll
    for (int i = 0; i < 8; i++) acc[i] = 0.f;

    // Self-loop term: quarter 0 handles it (reduction folds it in).
    if (q == 0) {
        float d  = dis[wid];
        float sn = d * d;
        uint4 raw = *(const uint4*)&A[(size_t)wid * HD + col];
        const __half2* h = (const __half2*)&raw;
        #pragma unroll
        for (int i = 0; i < 4; i++) {
            float2 f = __half22float2(h[i]);
            acc[2 * i]     = f.x * sn;
            acc[2 * i + 1] = f.y * sn;
        }
    }

    int e0 = rowstart[wid];
    int e1 = rowstart[wid + 1];

    // Software pipeline: index for iteration k+1 is loaded before iteration k's FMAs.
    int  e     = e0 + q;
    bool valid = e < e1;
    int2 p = valid ? epack[e] : make_int2(0, 0);

    while (valid) {
        int   s = p.x;
        float w = __int_as_float(p.y);
        uint4 raw = *(const uint4*)&A[(size_t)s * HD + col];

        int  e2 = e + 4;
        bool v2 = e2 < e1;
        if (v2) p = epack[e2];      // prefetch next (src, w) while raw is in flight

        const __half2* h = (const __half2*)&raw;
        #pragma unroll
        for (int i = 0; i < 4; i++) {
            float2 f = __half22float2(h[i]);
            acc[2 * i]     = fmaf(f.x, w, acc[2 * i]);
            acc[2 * i + 1] = fmaf(f.y, w, acc[2 * i + 1]);
        }
        e = e2;
        valid = v2;
    }

    // Reduce the 4 quarters.
    #pragma unroll
    for (int i = 0; i < 8; i++) {
        acc[i] += __shfl_xor_sync(0xffffffffu, acc[i], 8);
        acc[i] += __shfl_xor_sync(0xffffffffu, acc[i], 16);
    }

    if (q == 0) {
        float4 b0 = *(const float4*)&bias[col];
        float4 b1 = *(const float4*)&bias[col + 4];
        float4 r0 = make_float4(acc[0] + b0.x, acc[1] + b0.y, acc[2] + b0.z, acc[3] + b0.w);
        float4 r1 = make_float4(acc[4] + b1.x, acc[5] + b1.y, acc[6] + b1.z, acc[7] + b1.w);
        *(float4*)&Y[(size_t)wid * HD + col]     = r0;
        *(float4*)&Y[(size_t)wid * HD + col + 4] = r1;
    }
}

// ---------------- launch ----------------
extern "C" void kernel_launch(void* const* d_in, const int* in_sizes, int n_in,
                              void* d_out, int out_size) {
    const float* x  = (const float*)d_in[0];
    const void*  ei = d_in[1];   // [2,E]; dtype sniffed on device (int32 vs int64)
    const float* W1 = (const float*)d_in[3];
    const float* b1 = (const float*)d_in[4];
    const float* W2 = (const float*)d_in[5];
    const float* b2 = (const float*)d_in[6];
    const float* W3 = (const float*)d_in[7];
    const float* b3 = (const float*)d_in[8];

    int n = in_sizes[0] / HD;   // 100000
    int e = in_sizes[1] / 2;    // 1600000

    int*    src32;    cudaGetSymbolAddress((void**)&src32, g_src32);
    int*    dst32;    cudaGetSymbolAddress((void**)&dst32, g_dst32);
    int*    cnt;      cudaGetSymbolAddress((void**)&cnt, g_cnt);
    int*    rowstart; cudaGetSymbolAddress((void**)&rowstart, g_rowstart);
    int*    cursor;   cudaGetSymbolAddress((void**)&cursor, g_cursor);
    float*  dis;      cudaGetSymbolAddress((void**)&dis, g_dis);
    int*    blocksum; cudaGetSymbolAddress((void**)&blocksum, g_blocksum);
    int*    blockoff; cudaGetSymbolAddress((void**)&blockoff, g_blockoff);
    int2*   epack;    cudaGetSymbolAddress((void**)&epack, g_epack);
    __half* bufAh;    cudaGetSymbolAddress((void**)&bufAh, g_bufAh);
    float*  bufB;     cudaGetSymbolAddress((void**)&bufB, g_bufB);
    float*  out = (float*)d_out;

    int nb_n = (n + 255) / 256;
    int nb_e = (e + 255) / 256;
    int nb_g = (n * 32 + 255) / 256;               // one warp per node
    int nb_m = (n + GROWS - 1) / GROWS;            // 64-row GEMM tiles
    int nb_s = (n + SCAN_CHUNK - 1) / SCAN_CHUNK;  // 98 scan blocks

    // ---- edge index normalization + CSR build (once per call) ----
    k_detect<<<1, 256>>>(ei);
    k_zero_int<<<nb_n, 256>>>(cnt, n);
    k_convhist<<<nb_e, 256>>>(ei, e, n, cnt);
    k_scan1<<<nb_s, SCAN_CHUNK>>>(cnt, rowstart, blocksum, dis, n);
    k_scan2<<<1, MAX_SCAN_BLOCKS>>>(blocksum, blockoff, nb_s, rowstart, n);
    k_scan3<<<nb_s, SCAN_CHUNK>>>(rowstart, cursor, blockoff, n);
    k_fill<<<nb_e, 256>>>(src32, dst32, e, n, dis, cursor, epack);

    // ---- layer 1 ----
    k_gemm_tc<<<nb_m, 128>>>(x, W1, bufAh, n, 0);
    k_gather<<<nb_g, 256>>>(bufAh, rowstart, epack, dis, b1, bufB, n);
    // ---- layer 2 (ReLU fused into GEMM input load) ----
    k_gemm_tc<<<nb_m, 128>>>(bufB, W2, bufAh, n, 1);
    k_gather<<<nb_g, 256>>>(bufAh, rowstart, epack, dis, b2, bufB, n);
    // ---- layer 3 ----
    k_gemm_tc<<<nb_m, 128>>>(bufB, W3, bufAh, n, 1);
    k_gather<<<nb_g, 256>>>(bufAh, rowstart, epack, dis, b3, out, n);
}